// round 3
// baseline (speedup 1.0000x reference)
#include <cuda_runtime.h>
#include <math.h>

#define TT 128
#define LL 4
#define BB 64
#define HH 512
#define GG 16
#define FF 64
#define NCTA 128
#define FIVEH (5*HH)
#define MTOT (BB*TT)

// ---------------- scratch (device globals; no allocations anywhere) ----------
__device__ float g_hh[(TT+1)*LL*BB*HH];   // h history; slot 0 = zeros (t = -1)
__device__ float g_c[LL*BB*HH];           // cell state
__device__ float g_xg[TT*LL*BB*GG];       // grouped inputs, nan->0
__device__ unsigned char g_z[TT*LL*BB];   // any-valid flag per (t,k,b)
__device__ float g_bt[LL*TT];             // (boundary > 0.5) ? 1 : 0
__device__ float g_part[TT*LL*NCTA];      // per-stage sg partial sums
__device__ float g_R1[LL*MTOT*HH];        // sigmoid(Hcat @ Q_k)
__device__ float g_excited[MTOT*HH];      // relu(sum_k mul1*h)

__device__ __forceinline__ float sigf(float x){ return 1.f/(1.f+expf(-x)); }
__device__ __forceinline__ float clip01(float x){ return fminf(fmaxf(x,0.f),1.f); }

// ---------------- preprocessing ----------------------------------------------
__global__ void prep_zero_kernel(){
  int idx = blockIdx.x*blockDim.x + threadIdx.x;   // L*B*H = 131072
  if (idx < LL*BB*HH){ g_hh[idx] = 0.f; g_c[idx] = 0.f; }
}

__global__ void prep_in_kernel(const float* __restrict__ inp,
                               const float* __restrict__ boundary){
  int idx = blockIdx.x*blockDim.x + threadIdx.x;   // T*L*B = 32768
  if (idx < TT*LL*BB){
    int b  = idx % BB;
    int kk = (idx / BB) % LL;
    int t  = idx / (BB*LL);
    const float* src = inp + (b*TT + t)*FF + kk*GG;
    bool any = false;
    #pragma unroll
    for (int j = 0; j < GG; j++){
      float v = src[j];
      bool nn = (v != v);
      any = any || (!nn);
      g_xg[idx*GG + j] = nn ? 0.f : v;
    }
    g_z[idx] = any ? 1 : 0;
  }
  if (idx < LL*TT) g_bt[idx] = (boundary[idx] > 0.5f) ? 1.f : 0.f;
}

// ---------------- recurrence: K-blocked GEMM helper --------------------------
template<int NG>
__device__ __forceinline__ int grp(int gi){
  if (NG == 4) return (gi == 3) ? 4 : gi;        // f,g,i,sg
  else         return (gi == 0) ? 1 : ((gi == 1) ? 2 : 4);  // g,i,sg
}

// mm: 0 = unmasked, 1 = keep only z-rows, 2 = keep only !z-rows
template<int NG>
__device__ __forceinline__ void gemm_block(
    const float* __restrict__ a, int astr,
    const float* __restrict__ w, int wstr, int len, int mm,
    int h0, int tid, float (&acc)[2][4],
    float (*Ash)[33], float (*Wsh)[33], const unsigned char* zsh)
{
  const int tx = tid & 3, ty = tid >> 2;
  for (int j0 = 0; j0 < len; j0 += 32){
    int cw = len - j0; if (cw > 32) cw = 32;     // 32 or 16, both pow2
    const int sh = (cw == 32) ? 5 : 4, msk = cw - 1;
    for (int idx = tid; idx < 64*cw; idx += 128){
      int j = idx & msk, bb = idx >> sh;
      float v = a[bb*astr + j0 + j];
      if (mm == 1)      v = zsh[bb] ? v   : 0.f;
      else if (mm == 2) v = zsh[bb] ? 0.f : v;
      Ash[bb][j] = v;
    }
    for (int idx = tid; idx < NG*4*cw; idx += 128){
      int j = idx & msk, ci = idx >> sh;
      int n = grp<NG>(ci >> 2)*HH + h0 + (ci & 3);
      Wsh[ci][j] = w[n*wstr + j0 + j];
    }
    __syncthreads();
    #pragma unroll 4
    for (int j = 0; j < cw; j++){
      float a0 = Ash[ty][j], a1 = Ash[ty+32][j];
      #pragma unroll
      for (int gi = 0; gi < NG; gi++){
        float wv = Wsh[gi*4 + tx][j];
        acc[0][gi] += a0*wv;
        acc[1][gi] += a1*wv;
      }
    }
    __syncthreads();
  }
}

__global__ void __launch_bounds__(128) stage_kernel(
    int t, int k,
    const float* __restrict__ W, const float* __restrict__ Z,
    const float* __restrict__ U, const float* __restrict__ V,
    const float* __restrict__ J, const float* __restrict__ bvec)
{
  __shared__ float Ash[64][33];
  __shared__ float Wsh[16][33];
  __shared__ unsigned char zsh[64];
  __shared__ float red[128];
  __shared__ float sh2[2];

  const int tid = threadIdx.x;
  const int h0  = blockIdx.x * 4;
  const int st  = t*LL + k;

  // deterministic flag reduction over previous stages' 128 partials
  float pv = (t > 0) ? g_part[(st-LL)*NCTA + tid] : 0.f;
  float lv = (k > 0) ? g_part[(st-1 )*NCTA + tid] : 0.f;
  red[tid] = pv; __syncthreads();
  for (int s = 64; s > 0; s >>= 1){ if (tid < s) red[tid] += red[tid+s]; __syncthreads(); }
  if (tid == 0) sh2[0] = (t == 0) ? g_bt[k*TT] : ((red[0] > 0.5f*BB*HH) ? 1.f : 0.f);
  __syncthreads();
  red[tid] = lv; __syncthreads();
  for (int s = 64; s > 0; s >>= 1){ if (tid < s) red[tid] += red[tid+s]; __syncthreads(); }
  if (tid == 0) sh2[1] = (k == 0) ? g_bt[t] : ((red[0] > 0.5f*BB*HH) ? 1.f : 0.f);
  if (tid < 64) zsh[tid] = g_z[(t*LL + k)*BB + tid];
  __syncthreads();

  const bool p = (sh2[0] >= 0.5f), l = (sh2[1] >= 0.5f);
  const int mode = (!p && l) ? 1 : (p && !l) ? 2 : (p && l) ? 3 : 4;
  const float* bk = bvec + k*FIVEH;

  if (mode == 4){
    // no GEMM: h = sigmoid(b_o)*tanh(c); c, sg depend only on bias
    for (int idx = tid; idx < BB*4; idx += 128){
      int bb = idx >> 2, hc = h0 + (idx & 3);
      float o  = sigf(bk[3*HH + hc]);
      float cp = g_c[(k*BB + bb)*HH + hc];
      g_hh[(((t+1)*LL + k)*BB + bb)*HH + hc] = o * tanhf(cp);
    }
    if (tid == 0){
      float s4 = 0.f;
      #pragma unroll
      for (int c = 0; c < 4; c++) s4 += clip01((bk[4*HH + h0 + c] + 1.f)*0.5f);
      g_part[st*NCTA + blockIdx.x] = 64.f * s4;   // 64 identical rows, exact
    }
    return;
  }

  const int kn = (k+1 < LL) ? k+1 : LL-1;
  const float* hprev_k  = g_hh + ((t*LL + k )*BB)*HH;
  const float* hprev_kn = g_hh + ((t*LL + kn)*BB)*HH;
  const float* hlow     = g_hh + (((t+1)*LL + (k-1))*BB)*HH;  // valid for k>0
  const float* xg       = g_xg + (t*LL + k)*BB*GG;

  float acc[2][4] = {{0.f,0.f,0.f,0.f},{0.f,0.f,0.f,0.f}};

  if (mode == 1){
    gemm_block<4>(hprev_k, HH, W + (size_t)k*FIVEH*HH, HH, HH, 0, h0, tid, acc, Ash, Wsh, zsh);
    if (k > 0){
      gemm_block<4>(hlow, HH, U + (size_t)k*FIVEH*(HH+GG), HH+GG, HH, 1, h0, tid, acc, Ash, Wsh, zsh);
      gemm_block<4>(hlow, HH, V + (size_t)k*FIVEH*HH,      HH,    HH, 2, h0, tid, acc, Ash, Wsh, zsh);
    }
    gemm_block<4>(xg, GG, U + (size_t)k*FIVEH*(HH+GG) + HH, HH+GG, GG, 1, h0, tid, acc, Ash, Wsh, zsh);
  } else if (mode == 3){
    gemm_block<3>(hprev_kn, HH, Z + (size_t)k*FIVEH*HH, HH, HH, 0, h0, tid, acc, Ash, Wsh, zsh);
    if (k > 0){
      gemm_block<3>(hlow, HH, U + (size_t)k*FIVEH*(HH+GG), HH+GG, HH, 1, h0, tid, acc, Ash, Wsh, zsh);
      gemm_block<3>(hlow, HH, V + (size_t)k*FIVEH*HH,      HH,    HH, 2, h0, tid, acc, Ash, Wsh, zsh);
    }
    gemm_block<3>(xg, GG, U + (size_t)k*FIVEH*(HH+GG) + HH, HH+GG, GG, 1, h0, tid, acc, Ash, Wsh, zsh);
  } else { // mode 2
    gemm_block<3>(hprev_kn, HH, Z + (size_t)k*FIVEH*HH, HH, HH, 0, h0, tid, acc, Ash, Wsh, zsh);
    gemm_block<3>(xg, GG, J + (size_t)k*FIVEH*GG, GG, GG, 1, h0, tid, acc, Ash, Wsh, zsh);
  }

  // epilogue: thread (tx,ty) owns h-col h0+tx, rows ty and ty+32
  const int tx = tid & 3, ty = tid >> 2;
  const int hcol = h0 + tx;
  float sgsum = 0.f;
  #pragma unroll
  for (int r = 0; r < 2; r++){
    int bb = ty + 32*r;
    float cp = g_c[(k*BB + bb)*HH + hcol];
    float cn, ps;
    if (mode == 1){
      float f  = sigf (acc[r][0] + bk[hcol]);
      float gg = tanhf(acc[r][1] + bk[HH   + hcol]);
      float ii = sigf (acc[r][2] + bk[2*HH + hcol]);
      ps = acc[r][3] + bk[4*HH + hcol];
      cn = f*cp + ii*gg;
    } else {                           // modes 2/3: c = i*g
      float gg = tanhf(acc[r][0] + bk[HH   + hcol]);
      float ii = sigf (acc[r][1] + bk[2*HH + hcol]);
      ps = acc[r][2] + bk[4*HH + hcol];
      cn = ii*gg;
    }
    g_c[(k*BB + bb)*HH + hcol] = cn;
    // h unchanged in modes 1/2/3: copy forward
    g_hh[(((t+1)*LL + k)*BB + bb)*HH + hcol] = g_hh[((t*LL + k)*BB + bb)*HH + hcol];
    sgsum += clip01((ps + 1.f)*0.5f);
  }
  red[tid] = sgsum; __syncthreads();
  for (int s = 64; s > 0; s >>= 1){ if (tid < s) red[tid] += red[tid+s]; __syncthreads(); }
  if (tid == 0) g_part[st*NCTA + blockIdx.x] = red[0];
}

// ---------------- excitation -------------------------------------------------
// E1: g_R1[k][m][n] = sigmoid( sum_f Hcat[m][f] * Q[k][f][n] ), m = b*T + t
__global__ void __launch_bounds__(256) e1_kernel(const float* __restrict__ Q){
  __shared__ float Ash[64][33];
  __shared__ float Bsh[32][65];
  const int tid = threadIdx.x;
  const int n0 = blockIdx.x*64, m0 = blockIdx.y*64, kq = blockIdx.z;
  const int tx = tid & 15, ty = tid >> 4;
  float acc[4][4] = {};
  for (int f0 = 0; f0 < LL*HH; f0 += 32){
    const int kf = f0 >> 9, hf = f0 & (HH-1);
    for (int idx = tid; idx < 64*32; idx += 256){
      int j = idx & 31, mi = idx >> 5;
      int m = m0 + mi, b = m >> 7, tt = m & 127;
      Ash[mi][j] = g_hh[(size_t)(((tt+1)*LL + kf)*BB + b)*HH + hf + j];
    }
    for (int idx = tid; idx < 32*64; idx += 256){
      int n = idx & 63, j = idx >> 6;
      Bsh[j][n] = Q[(size_t)(kq*LL*HH + f0 + j)*HH + n0 + n];
    }
    __syncthreads();
    #pragma unroll 8
    for (int j = 0; j < 32; j++){
      float av[4], bv[4];
      #pragma unroll
      for (int r = 0; r < 4; r++) av[r] = Ash[ty + 16*r][j];
      #pragma unroll
      for (int c = 0; c < 4; c++) bv[c] = Bsh[j][tx + 16*c];
      #pragma unroll
      for (int r = 0; r < 4; r++)
        #pragma unroll
        for (int c = 0; c < 4; c++) acc[r][c] += av[r]*bv[c];
    }
    __syncthreads();
  }
  #pragma unroll
  for (int r = 0; r < 4; r++){
    int m = m0 + ty + 16*r;
    #pragma unroll
    for (int c = 0; c < 4; c++){
      int n = n0 + tx + 16*c;
      g_R1[((size_t)kq*MTOT + m)*HH + n] = sigf(acc[r][c]);
    }
  }
}

// E2: excited[m][n] = relu( sum_k (R1[k][m][:] @ R[k][:,n]) * h[k][m][n] )
__global__ void __launch_bounds__(256) e2_kernel(const float* __restrict__ Rm){
  __shared__ float Ash[64][33];
  __shared__ float Bsh[32][65];
  const int tid = threadIdx.x;
  const int n0 = blockIdx.x*64, m0 = blockIdx.y*64;
  const int tx = tid & 15, ty = tid >> 4;
  float tot[4][4] = {};
  for (int kq = 0; kq < LL; kq++){
    float acc[4][4] = {};
    for (int f0 = 0; f0 < HH; f0 += 32){
      for (int idx = tid; idx < 64*32; idx += 256){
        int j = idx & 31, mi = idx >> 5;
        Ash[mi][j] = g_R1[((size_t)kq*MTOT + m0 + mi)*HH + f0 + j];
      }
      for (int idx = tid; idx < 32*64; idx += 256){
        int n = idx & 63, j = idx >> 6;
        Bsh[j][n] = Rm[(size_t)(kq*HH + f0 + j)*HH + n0 + n];
      }
      __syncthreads();
      #pragma unroll 8
      for (int j = 0; j < 32; j++){
        float av[4], bv[4];
        #pragma unroll
        for (int r = 0; r < 4; r++) av[r] = Ash[ty + 16*r][j];
        #pragma unroll
        for (int c = 0; c < 4; c++) bv[c] = Bsh[j][tx + 16*c];
        #pragma unroll
        for (int r = 0; r < 4; r++)
          #pragma unroll
          for (int c = 0; c < 4; c++) acc[r][c] += av[r]*bv[c];
      }
      __syncthreads();
    }
    #pragma unroll
    for (int r = 0; r < 4; r++){
      int m = m0 + ty + 16*r, b = m >> 7, tt = m & 127;
      #pragma unroll
      for (int c = 0; c < 4; c++){
        int n = n0 + tx + 16*c;
        tot[r][c] += acc[r][c] * g_hh[(size_t)(((tt+1)*LL + kq)*BB + b)*HH + n];
      }
    }
  }
  #pragma unroll
  for (int r = 0; r < 4; r++){
    int m = m0 + ty + 16*r;
    #pragma unroll
    for (int c = 0; c < 4; c++){
      int n = n0 + tx + 16*c;
      g_excited[(size_t)m*HH + n] = fmaxf(tot[r][c], 0.f);
    }
  }
}

// E3: out[m][f] = excited[m][:] @ Wo[f][:] + bo[f]
__global__ void __launch_bounds__(256) e3_kernel(const float* __restrict__ Wo,
                                                 const float* __restrict__ bo,
                                                 float* __restrict__ out){
  __shared__ float Ash[64][33];
  __shared__ float Bsh[32][65];
  const int tid = threadIdx.x;
  const int m0 = blockIdx.x*64;
  const int tx = tid & 15, ty = tid >> 4;
  float acc[4][4] = {};
  for (int f0 = 0; f0 < HH; f0 += 32){
    for (int idx = tid; idx < 64*32; idx += 256){
      int j = idx & 31, mi = idx >> 5;
      Ash[mi][j] = g_excited[(size_t)(m0 + mi)*HH + f0 + j];
    }
    for (int idx = tid; idx < 64*32; idx += 256){
      int j = idx & 31, n = idx >> 5;      // coalesced along Wo rows
      Bsh[j][n] = Wo[(size_t)n*HH + f0 + j];
    }
    __syncthreads();
    #pragma unroll 8
    for (int j = 0; j < 32; j++){
      float av[4], bv[4];
      #pragma unroll
      for (int r = 0; r < 4; r++) av[r] = Ash[ty + 16*r][j];
      #pragma unroll
      for (int c = 0; c < 4; c++) bv[c] = Bsh[j][tx + 16*c];
      #pragma unroll
      for (int r = 0; r < 4; r++)
        #pragma unroll
        for (int c = 0; c < 4; c++) acc[r][c] += av[r]*bv[c];
    }
    __syncthreads();
  }
  #pragma unroll
  for (int r = 0; r < 4; r++){
    int m = m0 + ty + 16*r;
    #pragma unroll
    for (int c = 0; c < 4; c++){
      int n = tx + 16*c;                   // F = 64
      out[(size_t)m*FF + n] = acc[r][c] + bo[n];
    }
  }
}

// ---------------- launch -----------------------------------------------------
extern "C" void kernel_launch(void* const* d_in, const int* in_sizes, int n_in,
                              void* d_out, int out_size) {
  const float* inp      = (const float*)d_in[0];
  const float* W        = (const float*)d_in[1];
  const float* Z        = (const float*)d_in[2];
  const float* U        = (const float*)d_in[3];
  const float* V        = (const float*)d_in[4];
  const float* J        = (const float*)d_in[5];
  const float* bvec     = (const float*)d_in[6];
  const float* boundary = (const float*)d_in[7];
  const float* Q        = (const float*)d_in[8];
  const float* Rm       = (const float*)d_in[9];
  const float* Wo       = (const float*)d_in[10];
  const float* bo       = (const float*)d_in[11];
  float* out            = (float*)d_out;

  prep_zero_kernel<<<512, 256>>>();
  prep_in_kernel<<<128, 256>>>(inp, boundary);

  for (int t = 0; t < TT; t++)
    for (int k = 0; k < LL; k++)
      stage_kernel<<<NCTA, 128>>>(t, k, W, Z, U, V, J, bvec);

  e1_kernel<<<dim3(8, 128, 4), 256>>>(Q);
  e2_kernel<<<dim3(8, 128), 256>>>(Rm);
  e3_kernel<<<128, 256>>>(Wo, bo, out);
}

// round 5
// speedup vs baseline: 2.5062x; 2.5062x over previous
#include <cuda_runtime.h>
#include <math.h>

#define TT 128
#define LL 4
#define BB 64
#define HH 512
#define GG 16
#define FF 64
#define NREC 128
#define FIVEH (5*HH)
#define MTOT (BB*TT)

// ---------------- scratch (device globals; no allocations) -------------------
__device__ float g_hh[(size_t)(TT+1)*LL*BB*HH];   // h history; slot 0 = zeros
__device__ float g_c[LL*BB*HH];
__device__ float g_xg[TT*LL*BB*GG];
__device__ unsigned char g_z[TT*LL*BB];
__device__ unsigned char g_allz[TT*LL];
__device__ float g_bt[LL*TT];
__device__ float g_part[TT*LL*NREC];
__device__ float g_pp[4*BB*4*HH];                 // [split][b][loc*H + h]
__device__ unsigned int g_bar;
__device__ float g_R1[(size_t)LL*MTOT*HH];
__device__ float g_excited[(size_t)MTOT*HH];

__device__ __forceinline__ float sigf(float x){ return 1.f/(1.f+expf(-x)); }
__device__ __forceinline__ float clip01(float x){ return fminf(fmaxf(x,0.f),1.f); }

// ---------------- shared inner product: 4x4 per thread -----------------------
__device__ __forceinline__ void mm_inner(const float (*Ash)[68], const float (*Bsh)[68],
                                         int cw, int ty, int tx, float (&acc)[4][4]){
  #pragma unroll 8
  for (int j = 0; j < cw; j++){
    float4 av = *(const float4*)&Ash[j][ty*4];
    float4 bv = *(const float4*)&Bsh[j][tx*4];
    acc[0][0] += av.x*bv.x; acc[0][1] += av.x*bv.y; acc[0][2] += av.x*bv.z; acc[0][3] += av.x*bv.w;
    acc[1][0] += av.y*bv.x; acc[1][1] += av.y*bv.y; acc[1][2] += av.y*bv.z; acc[1][3] += av.y*bv.w;
    acc[2][0] += av.z*bv.x; acc[2][1] += av.z*bv.y; acc[2][2] += av.z*bv.z; acc[2][3] += av.z*bv.w;
    acc[3][0] += av.w*bv.x; acc[3][1] += av.w*bv.y; acc[3][2] += av.w*bv.z; acc[3][3] += av.w*bv.w;
  }
}

// transpose-load A (64 x CW, K-contig rows) and B (64 weight rows x CW) into smem
template<int CW>
__device__ __forceinline__ void load_tiles_T(
    const float* __restrict__ A, int lda, int mm, const unsigned char* zsh, int jba,
    const float* __restrict__ Wr, int wstr, int jbw,
    int tid, float (*Ash)[68], float (*Bsh)[68])
{
  const int QP = CW/4;
  const int NF4 = 64*QP;
  #pragma unroll
  for (int id = tid; id < NF4; id += 256){
    int row = id / QP, q = id - row*QP;
    float4 v = *(const float4*)&A[(size_t)row*lda + jba + q*4];
    if (mm == 1){ if (!zsh[row]) v = make_float4(0.f,0.f,0.f,0.f); }
    else if (mm == 2){ if (zsh[row]) v = make_float4(0.f,0.f,0.f,0.f); }
    int jj = q*4;
    Ash[jj][row]=v.x; Ash[jj+1][row]=v.y; Ash[jj+2][row]=v.z; Ash[jj+3][row]=v.w;
  }
  #pragma unroll
  for (int id = tid; id < NF4; id += 256){
    int n = id / QP, q = id - n*QP;
    float4 v = *(const float4*)&Wr[(size_t)n*wstr + jbw + q*4];
    int jj = q*4;
    Bsh[jj][n]=v.x; Bsh[jj+1][n]=v.y; Bsh[jj+2][n]=v.z; Bsh[jj+3][n]=v.w;
  }
}

// ---------------- preprocessing ----------------------------------------------
__global__ void prep_zero_kernel(){
  int idx = blockIdx.x*blockDim.x + threadIdx.x;
  if (idx < LL*BB*HH){ g_hh[idx] = 0.f; g_c[idx] = 0.f; }
  if (idx == 0) g_bar = 0u;
}

__global__ void prep_in_kernel(const float* __restrict__ inp,
                               const float* __restrict__ boundary){
  int idx = blockIdx.x*blockDim.x + threadIdx.x;
  if (idx < TT*LL*BB){
    int b  = idx % BB;
    int kk = (idx / BB) % LL;
    int t  = idx / (BB*LL);
    const float* src = inp + (b*TT + t)*FF + kk*GG;
    bool any = false;
    #pragma unroll
    for (int j = 0; j < GG; j++){
      float v = src[j];
      bool nn = (v != v);
      any = any || (!nn);
      g_xg[idx*GG + j] = nn ? 0.f : v;
    }
    g_z[idx] = any ? 1 : 0;
  }
  if (idx < LL*TT) g_bt[idx] = (boundary[idx] > 0.5f) ? 1.f : 0.f;
}

__global__ void prep_allz_kernel(){
  int st = blockIdx.x*blockDim.x + threadIdx.x;
  if (st < TT*LL){
    unsigned char a = 1;
    for (int b = 0; b < BB; b++) a = (unsigned char)(a & g_z[st*BB + b]);
    g_allz[st] = a;
  }
}

// ---------------- grid barrier (all 128 CTAs co-resident) --------------------
__device__ __forceinline__ void gbar(unsigned int tgt){
  __syncthreads();
  if (threadIdx.x == 0){
    __threadfence();
    atomicAdd(&g_bar, 1u);
    while (*((volatile unsigned int*)&g_bar) < tgt) __nanosleep(32);
  }
  __syncthreads();
  __threadfence();   // gpu-scope fence: invalidates L1D -> see peers' writes
}

// ---------------- persistent recurrence --------------------------------------
__global__ void __launch_bounds__(256,1) recur_kernel(
    const float* __restrict__ W, const float* __restrict__ Z,
    const float* __restrict__ U, const float* __restrict__ V,
    const float* __restrict__ J, const float* __restrict__ bvec)
{
  __shared__ float Ash[32][68];
  __shared__ float Bsh[32][68];
  __shared__ float red[256];
  __shared__ float sflag[2];
  __shared__ unsigned char zsh[64];

  const int tid = threadIdx.x;
  const int cta = blockIdx.x;
  const int tx = tid & 15, ty = tid >> 4;
  unsigned int tgt = 0;

  for (int st = 0; st < TT*LL; st++){
    const int t = st >> 2, k = st & 3;

    // ---- flags (each CTA reduces identically -> identical mode) ----
    float v = (t > 0 && tid < NREC) ? g_part[(st-LL)*NREC + tid] : 0.f;
    red[tid] = v; __syncthreads();
    #pragma unroll
    for (int s = 128; s > 0; s >>= 1){ if (tid < s) red[tid] += red[tid+s]; __syncthreads(); }
    if (tid == 0) sflag[0] = (t == 0) ? g_bt[k*TT] : ((red[0] > 16384.f) ? 1.f : 0.f);
    __syncthreads();
    v = (k > 0 && tid < NREC) ? g_part[(st-1)*NREC + tid] : 0.f;
    red[tid] = v; __syncthreads();
    #pragma unroll
    for (int s = 128; s > 0; s >>= 1){ if (tid < s) red[tid] += red[tid+s]; __syncthreads(); }
    if (tid == 0) sflag[1] = (k == 0) ? g_bt[t] : ((red[0] > 16384.f) ? 1.f : 0.f);
    if (tid < 64) zsh[tid] = g_z[st*BB + tid];
    __syncthreads();

    const bool p = sflag[0] >= 0.5f, l = sflag[1] >= 0.5f;
    const int mode = (!p && l) ? 1 : ((p && !l) ? 2 : ((p && l) ? 3 : 4));
    const float* bk = bvec + k*FIVEH;
    const int e = cta*256 + tid, eb = e >> 9, eh = e & 511;

    if (mode == 4){
      // no GEMM: h = sigmoid(b_o)*tanh(c); c unchanged; sg from bias only
      float o  = sigf(bk[3*HH + eh]);
      float cp = g_c[(k*BB + eb)*HH + eh];
      g_hh[((size_t)((t+1)*LL + k)*BB + eb)*HH + eh] = o * tanhf(cp);
      float sgv = clip01((bk[4*HH + eh] + 1.f)*0.5f);
      red[tid] = sgv; __syncthreads();
      #pragma unroll
      for (int s = 128; s > 0; s >>= 1){ if (tid < s) red[tid] += red[tid+s]; __syncthreads(); }
      if (tid == 0) g_part[st*NREC + cta] = red[0];
      tgt += NREC; gbar(tgt);
      continue;
    }

    const int ng = (mode == 1) ? 4 : 3;
    const int nT = ng*8;
    const bool az = (g_allz[st] != 0);

    if (cta < nT*4){
      const int split = cta / nT, ntile = cta - split*nT;
      const int n0 = ntile*64, loc = n0 >> 9, h0 = n0 & 511;
      const int g = (mode == 1) ? ((loc == 3) ? 4 : loc)
                                : ((loc == 0) ? 1 : ((loc == 1) ? 2 : 4));
      const size_t wr0 = (size_t)(g*HH + h0);
      const int jb = split*128;
      float acc[4][4] = {{0.f,0.f,0.f,0.f},{0.f,0.f,0.f,0.f},{0.f,0.f,0.f,0.f},{0.f,0.f,0.f,0.f}};

      // K-concatenated blocks (128 rows each per split), single call site
      const float* bA[3]; const float* bW[3]; int bws[3]; int bmm[3]; int nb = 0;
      {
        const int km = (mode == 1) ? k : ((k+1 < LL) ? k+1 : LL-1);
        bA[nb] = g_hh + ((size_t)(t*LL + km)*BB)*HH;
        bW[nb] = ((mode == 1) ? W : Z) + (size_t)k*FIVEH*HH + wr0*HH;
        bws[nb] = HH; bmm[nb] = 0; nb++;
      }
      if (mode != 2 && k > 0){
        const float* hlow = g_hh + ((size_t)((t+1)*LL + (k-1))*BB)*HH;
        bA[nb] = hlow; bW[nb] = U + (size_t)k*FIVEH*(HH+GG) + wr0*(HH+GG);
        bws[nb] = HH+GG; bmm[nb] = az ? 0 : 1; nb++;
        if (!az){
          bA[nb] = hlow; bW[nb] = V + (size_t)k*FIVEH*HH + wr0*HH;
          bws[nb] = HH; bmm[nb] = 2; nb++;
        }
      }
      for (int bi = 0; bi < nb; bi++){
        const float* A = bA[bi]; const float* Wr = bW[bi];
        const int ws = bws[bi], mm = bmm[bi];
        for (int j0 = 0; j0 < 128; j0 += 32){
          load_tiles_T<32>(A, HH, mm, zsh, jb + j0, Wr, ws, jb + j0, tid, Ash, Bsh);
          __syncthreads();
          mm_inner(Ash, Bsh, 32, ty, tx, acc);
          __syncthreads();
        }
      }
      if (split == 0){
        // xg block (K=16); x rows of !z batches are zero -> no mask needed
        const float* A = g_xg + (size_t)st*BB*GG;
        const float* Wr; int ws, jbw;
        if (mode != 2){ Wr = U + (size_t)k*FIVEH*(HH+GG) + wr0*(HH+GG); ws = HH+GG; jbw = HH; }
        else          { Wr = J + (size_t)k*FIVEH*GG + wr0*GG;           ws = GG;    jbw = 0;  }
        load_tiles_T<16>(A, GG, 0, zsh, 0, Wr, ws, jbw, tid, Ash, Bsh);
        __syncthreads();
        mm_inner(Ash, Bsh, 16, ty, tx, acc);
        __syncthreads();
      }
      #pragma unroll
      for (int r = 0; r < 4; r++){
        float4 o = make_float4(acc[r][0], acc[r][1], acc[r][2], acc[r][3]);
        *(float4*)&g_pp[((size_t)split*BB + ty*4 + r)*(4*HH) + n0 + tx*4] = o;
      }
    }
    tgt += NREC; gbar(tgt);

    // ---- epilogue: one element per thread; fixed-order split reduce ----
    {
      const size_t pb = (size_t)eb*(4*HH) + eh;
      const size_t sp = (size_t)BB*4*HH;
      float a0 = ((g_pp[pb]        + g_pp[sp + pb])        + g_pp[2*sp + pb])        + g_pp[3*sp + pb];
      float a1 = ((g_pp[pb+HH]     + g_pp[sp + pb+HH])     + g_pp[2*sp + pb+HH])     + g_pp[3*sp + pb+HH];
      float a2 = ((g_pp[pb+2*HH]   + g_pp[sp + pb+2*HH])   + g_pp[2*sp + pb+2*HH])   + g_pp[3*sp + pb+2*HH];
      float a3 = 0.f;
      if (ng == 4)
        a3 = ((g_pp[pb+3*HH] + g_pp[sp + pb+3*HH]) + g_pp[2*sp + pb+3*HH]) + g_pp[3*sp + pb+3*HH];

      float cp = g_c[(k*BB + eb)*HH + eh];
      float cn, ps;
      if (mode == 1){
        float f  = sigf (a0 + bk[eh]);
        float gg = tanhf(a1 + bk[HH + eh]);
        float ii = sigf (a2 + bk[2*HH + eh]);
        ps = a3 + bk[4*HH + eh];
        cn = f*cp + ii*gg;
      } else {
        float gg = tanhf(a0 + bk[HH + eh]);
        float ii = sigf (a1 + bk[2*HH + eh]);
        ps = a2 + bk[4*HH + eh];
        cn = ii*gg;
      }
      g_c[(k*BB + eb)*HH + eh] = cn;
      g_hh[((size_t)((t+1)*LL + k)*BB + eb)*HH + eh] =
          g_hh[((size_t)(t*LL + k)*BB + eb)*HH + eh];       // h unchanged
      float sgv = clip01((ps + 1.f)*0.5f);
      red[tid] = sgv; __syncthreads();
      #pragma unroll
      for (int s = 128; s > 0; s >>= 1){ if (tid < s) red[tid] += red[tid+s]; __syncthreads(); }
      if (tid == 0) g_part[st*NREC + cta] = red[0];
    }
    tgt += NREC; gbar(tgt);
  }
}

// ---------------- excitation -------------------------------------------------
// E1: R1[kq][m][h] = sigmoid( Hcat[m][:] @ Q[kq][:, h] ), M=8192 K=2048 N=2048
__global__ void __launch_bounds__(256) e1_kernel(const float* __restrict__ Q){
  __shared__ float Ash[32][68];
  __shared__ float Bsh[32][68];
  const int tid = threadIdx.x, tx = tid & 15, ty = tid >> 4;
  const int n0 = blockIdx.x*64, m0 = blockIdx.y*64;
  const int kq = n0 >> 9, nh0 = n0 & 511;
  const int bB = m0 >> 7, t0 = m0 & 127;
  float acc[4][4] = {{0.f,0.f,0.f,0.f},{0.f,0.f,0.f,0.f},{0.f,0.f,0.f,0.f},{0.f,0.f,0.f,0.f}};
  for (int f0 = 0; f0 < LL*HH; f0 += 32){
    const int kf = f0 >> 9, hf = f0 & 511;
    const float* abase = g_hh + ((size_t)(t0+1)*LL + kf)*BB*HH + (size_t)bB*HH + hf;
    #pragma unroll
    for (int id = tid; id < 512; id += 256){
      int mi = id >> 3, q = id & 7;
      float4 v = *(const float4*)(abase + (size_t)mi*(LL*BB*HH) + q*4);
      int jj = q*4;
      Ash[jj][mi]=v.x; Ash[jj+1][mi]=v.y; Ash[jj+2][mi]=v.z; Ash[jj+3][mi]=v.w;
    }
    #pragma unroll
    for (int id = tid; id < 512; id += 256){
      int j = id >> 4, qn = id & 15;
      float4 v = *(const float4*)&Q[((size_t)kq*(LL*HH) + f0 + j)*HH + nh0 + qn*4];
      *(float4*)&Bsh[j][qn*4] = v;
    }
    __syncthreads();
    mm_inner(Ash, Bsh, 32, ty, tx, acc);
    __syncthreads();
  }
  #pragma unroll
  for (int r = 0; r < 4; r++){
    float4 o = make_float4(sigf(acc[r][0]), sigf(acc[r][1]), sigf(acc[r][2]), sigf(acc[r][3]));
    *(float4*)&g_R1[((size_t)kq*MTOT + m0 + ty*4 + r)*HH + nh0 + tx*4] = o;
  }
}

// E2: excited[m][n] = relu( sum_k (R1[k][m][:] @ R[k][:,n]) * h[k][m][n] )
__global__ void __launch_bounds__(256) e2_kernel(const float* __restrict__ Rm){
  __shared__ float Ash[32][68];
  __shared__ float Bsh[32][68];
  const int tid = threadIdx.x, tx = tid & 15, ty = tid >> 4;
  const int n0 = blockIdx.x*64, m0 = blockIdx.y*64;
  const int bB = m0 >> 7, t0 = m0 & 127;
  float tot[4][4] = {{0.f,0.f,0.f,0.f},{0.f,0.f,0.f,0.f},{0.f,0.f,0.f,0.f},{0.f,0.f,0.f,0.f}};
  for (int kq = 0; kq < LL; kq++){
    float acc[4][4] = {{0.f,0.f,0.f,0.f},{0.f,0.f,0.f,0.f},{0.f,0.f,0.f,0.f},{0.f,0.f,0.f,0.f}};
    for (int f0 = 0; f0 < HH; f0 += 32){
      #pragma unroll
      for (int id = tid; id < 512; id += 256){
        int mi = id >> 3, q = id & 7;
        float4 v = *(const float4*)&g_R1[((size_t)kq*MTOT + m0 + mi)*HH + f0 + q*4];
        int jj = q*4;
        Ash[jj][mi]=v.x; Ash[jj+1][mi]=v.y; Ash[jj+2][mi]=v.z; Ash[jj+3][mi]=v.w;
      }
      #pragma unroll
      for (int id = tid; id < 512; id += 256){
        int j = id >> 4, qn = id & 15;
        float4 v = *(const float4*)&Rm[((size_t)kq*HH + f0 + j)*HH + n0 + qn*4];
        *(float4*)&Bsh[j][qn*4] = v;
      }
      __syncthreads();
      mm_inner(Ash, Bsh, 32, ty, tx, acc);
      __syncthreads();
    }
    #pragma unroll
    for (int r = 0; r < 4; r++){
      int tcur = t0 + ty*4 + r;
      float4 hv = *(const float4*)&g_hh[((size_t)(tcur+1)*LL + kq)*BB*HH + (size_t)bB*HH + n0 + tx*4];
      tot[r][0] += acc[r][0]*hv.x; tot[r][1] += acc[r][1]*hv.y;
      tot[r][2] += acc[r][2]*hv.z; tot[r][3] += acc[r][3]*hv.w;
    }
  }
  #pragma unroll
  for (int r = 0; r < 4; r++){
    float4 o = make_float4(fmaxf(tot[r][0],0.f), fmaxf(tot[r][1],0.f),
                           fmaxf(tot[r][2],0.f), fmaxf(tot[r][3],0.f));
    *(float4*)&g_excited[(size_t)(m0 + ty*4 + r)*HH + n0 + tx*4] = o;
  }
}

// E3: out[m][n] = excited[m][:] @ Wo[n][:] + bo[n]   (N = F = 64)
__global__ void __launch_bounds__(256) e3_kernel(const float* __restrict__ Wo,
                                                 const float* __restrict__ bo,
                                                 float* __restrict__ out){
  __shared__ float Ash[32][68];
  __shared__ float Bsh[32][68];
  const int tid = threadIdx.x, tx = tid & 15, ty = tid >> 4;
  const int m0 = blockIdx.x*64;
  float acc[4][4] = {{0.f,0.f,0.f,0.f},{0.f,0.f,0.f,0.f},{0.f,0.f,0.f,0.f},{0.f,0.f,0.f,0.f}};
  for (int f0 = 0; f0 < HH; f0 += 32){
    load_tiles_T<32>(g_excited + (size_t)m0*HH, HH, 0, (const unsigned char*)g_z, f0,
                     Wo, HH, f0, tid, Ash, Bsh);
    __syncthreads();
    mm_inner(Ash, Bsh, 32, ty, tx, acc);
    __syncthreads();
  }
  #pragma unroll
  for (int r = 0; r < 4; r++){
    int n = tx*4;
    float4 o = make_float4(acc[r][0] + bo[n], acc[r][1] + bo[n+1],
                           acc[r][2] + bo[n+2], acc[r][3] + bo[n+3]);
    *(float4*)&out[(size_t)(m0 + ty*4 + r)*FF + n] = o;
  }
}

// ---------------- launch -----------------------------------------------------
extern "C" void kernel_launch(void* const* d_in, const int* in_sizes, int n_in,
                              void* d_out, int out_size) {
  const float* inp      = (const float*)d_in[0];
  const float* W        = (const float*)d_in[1];
  const float* Z        = (const float*)d_in[2];
  const float* U        = (const float*)d_in[3];
  const float* V        = (const float*)d_in[4];
  const float* J        = (const float*)d_in[5];
  const float* bvec     = (const float*)d_in[6];
  const float* boundary = (const float*)d_in[7];
  const float* Q        = (const float*)d_in[8];
  const float* Rm       = (const float*)d_in[9];
  const float* Wo       = (const float*)d_in[10];
  const float* bo       = (const float*)d_in[11];
  float* out            = (float*)d_out;

  prep_zero_kernel<<<512, 256>>>();
  prep_in_kernel<<<128, 256>>>(inp, boundary);
  prep_allz_kernel<<<2, 256>>>();
  recur_kernel<<<NREC, 256>>>(W, Z, U, V, J, bvec);
  e1_kernel<<<dim3(32, 128), 256>>>(Q);
  e2_kernel<<<dim3(8, 128), 256>>>(Rm);
  e3_kernel<<<128, 256>>>(Wo, bo, out);
}

// round 10
// speedup vs baseline: 3.0397x; 1.2129x over previous
#include <cuda_runtime.h>
#include <cuda_bf16.h>
#include <mma.h>
#include <math.h>
#include <stdint.h>

using namespace nvcuda;

#define TT 128
#define LL 4
#define BB 64
#define HH 512
#define GG 16
#define FF 64
#define NREC 128
#define FIVEH (5*HH)
#define MTOT (BB*TT)   // 8192

// ---------------- scratch (device globals; no allocations) -------------------
__device__ float g_hh[(size_t)(TT+1)*LL*BB*HH];   // h history; slot 0 = zeros
__device__ float g_c[LL*BB*HH];
__device__ float g_xg[TT*LL*BB*GG];
__device__ unsigned char g_z[TT*LL*BB];
__device__ unsigned char g_allz[TT*LL];
__device__ float g_bt[LL*TT];
__device__ float g_part[TT*LL*NREC];
__device__ float g_pp[4*BB*4*HH];
__device__ unsigned int g_bar;
__device__ unsigned int g_flag1, g_flag2;         // wmma-mismatch flags
__device__ float g_excited[(size_t)MTOT*HH];

// bf16 split-precision buffers for the excitation GEMMs
__device__ __align__(128) __nv_bfloat16 g_Ahi[(size_t)MTOT*2048];
__device__ __align__(128) __nv_bfloat16 g_Alo[(size_t)MTOT*2048];
__device__ __align__(128) __nv_bfloat16 g_QThi[(size_t)LL*HH*2048];
__device__ __align__(128) __nv_bfloat16 g_QTlo[(size_t)LL*HH*2048];
__device__ __align__(128) __nv_bfloat16 g_R1hi[(size_t)LL*MTOT*HH];
__device__ __align__(128) __nv_bfloat16 g_R1lo[(size_t)LL*MTOT*HH];
__device__ __align__(128) __nv_bfloat16 g_RmThi[(size_t)LL*HH*HH];
__device__ __align__(128) __nv_bfloat16 g_RmTlo[(size_t)LL*HH*HH];
__device__ __align__(128) float g_mul1[(size_t)LL*MTOT*HH];

__device__ __forceinline__ float sigf(float x){ return 1.f/(1.f+expf(-x)); }
__device__ __forceinline__ float clip01(float x){ return fminf(fmaxf(x,0.f),1.f); }
__device__ __forceinline__ void bsplit(float x, __nv_bfloat16& hi, __nv_bfloat16& lo){
  hi = __float2bfloat16(x);
  lo = __float2bfloat16(x - __bfloat162float(hi));
}

// ---------------- WMMA split-bf16 GEMM core ----------------------------------
// CTA = 256 threads = 8 warps (4m x 2n), 128x128 tile, K chunk 32.
// D = (Ahi+Alo)(Bhi+Blo)^T via 3 products (hi*hi + lo*hi + hi*lo).
#define SPAD 40   // 80B rows; tile ptrs land on 32B multiples at 16-row offsets

using FragA = wmma::fragment<wmma::matrix_a,16,16,16,__nv_bfloat16,wmma::row_major>;
using FragB = wmma::fragment<wmma::matrix_b,16,16,16,__nv_bfloat16,wmma::col_major>;
using FragC = wmma::fragment<wmma::accumulator,16,16,16,float>;

__device__ __forceinline__ void wmma_core(
    __nv_bfloat16* sm,
    const __nv_bfloat16* __restrict__ Ah, const __nv_bfloat16* __restrict__ Al, int lda,
    const __nv_bfloat16* __restrict__ Bh, const __nv_bfloat16* __restrict__ Bl, int ldb,
    int ktot, FragC (&acc)[2][4])
{
  __nv_bfloat16* sAh = sm;
  __nv_bfloat16* sAl = sm +   128*SPAD;
  __nv_bfloat16* sBh = sm + 2*128*SPAD;
  __nv_bfloat16* sBl = sm + 3*128*SPAD;
  const int tid = threadIdx.x, wid = tid >> 5;
  const int wm = wid & 3, wn = wid >> 2;

  for (int kc = 0; kc < ktot; kc += 32){
    #pragma unroll
    for (int id = tid; id < 512; id += 256){
      int row = id >> 2, q = id & 3;
      *(uint4*)&sAh[row*SPAD + q*8] = *(const uint4*)&Ah[(size_t)row*lda + kc + q*8];
      *(uint4*)&sAl[row*SPAD + q*8] = *(const uint4*)&Al[(size_t)row*lda + kc + q*8];
      *(uint4*)&sBh[row*SPAD + q*8] = *(const uint4*)&Bh[(size_t)row*ldb + kc + q*8];
      *(uint4*)&sBl[row*SPAD + q*8] = *(const uint4*)&Bl[(size_t)row*ldb + kc + q*8];
    }
    __syncthreads();
    #pragma unroll
    for (int ks = 0; ks < 32; ks += 16){
      FragA fah[2], fal[2];
      #pragma unroll
      for (int mi = 0; mi < 2; mi++){
        wmma::load_matrix_sync(fah[mi], &sAh[(wm*32 + mi*16)*SPAD + ks], SPAD);
        wmma::load_matrix_sync(fal[mi], &sAl[(wm*32 + mi*16)*SPAD + ks], SPAD);
      }
      #pragma unroll
      for (int ni = 0; ni < 4; ni++){
        FragB fbh, fbl;
        wmma::load_matrix_sync(fbh, &sBh[(wn*64 + ni*16)*SPAD + ks], SPAD);
        wmma::load_matrix_sync(fbl, &sBl[(wn*64 + ni*16)*SPAD + ks], SPAD);
        #pragma unroll
        for (int mi = 0; mi < 2; mi++){
          wmma::mma_sync(acc[mi][ni], fah[mi], fbh, acc[mi][ni]);
          wmma::mma_sync(acc[mi][ni], fal[mi], fbh, acc[mi][ni]);
          wmma::mma_sync(acc[mi][ni], fah[mi], fbl, acc[mi][ni]);
        }
      }
    }
    __syncthreads();
  }
}

// ---------------- fp32 SIMT GEMM helpers -------------------------------------
__device__ __forceinline__ void mm_inner(const float (*Ash)[68], const float (*Bsh)[68],
                                         int cw, int ty, int tx, float (&acc)[4][4]){
  #pragma unroll 8
  for (int j = 0; j < cw; j++){
    float4 av = *(const float4*)&Ash[j][ty*4];
    float4 bv = *(const float4*)&Bsh[j][tx*4];
    acc[0][0] += av.x*bv.x; acc[0][1] += av.x*bv.y; acc[0][2] += av.x*bv.z; acc[0][3] += av.x*bv.w;
    acc[1][0] += av.y*bv.x; acc[1][1] += av.y*bv.y; acc[1][2] += av.y*bv.z; acc[1][3] += av.y*bv.w;
    acc[2][0] += av.z*bv.x; acc[2][1] += av.z*bv.y; acc[2][2] += av.z*bv.z; acc[2][3] += av.z*bv.w;
    acc[3][0] += av.w*bv.x; acc[3][1] += av.w*bv.y; acc[3][2] += av.w*bv.z; acc[3][3] += av.w*bv.w;
  }
}

template<int CW>
__device__ __forceinline__ void load_tiles_T(
    const float* __restrict__ A, int lda, int mm, const unsigned char* zsh, int jba,
    const float* __restrict__ Wr, int wstr, int jbw,
    int tid, float (*Ash)[68], float (*Bsh)[68])
{
  const int QP = CW/4;
  const int NF4 = 64*QP;
  #pragma unroll
  for (int id = tid; id < NF4; id += 256){
    int row = id / QP, q = id - row*QP;
    float4 v = *(const float4*)&A[(size_t)row*lda + jba + q*4];
    if (mm == 1){ if (!zsh[row]) v = make_float4(0.f,0.f,0.f,0.f); }
    else if (mm == 2){ if (zsh[row]) v = make_float4(0.f,0.f,0.f,0.f); }
    int jj = q*4;
    Ash[jj][row]=v.x; Ash[jj+1][row]=v.y; Ash[jj+2][row]=v.z; Ash[jj+3][row]=v.w;
  }
  #pragma unroll
  for (int id = tid; id < NF4; id += 256){
    int n = id / QP, q = id - n*QP;
    float4 v = *(const float4*)&Wr[(size_t)n*wstr + jbw + q*4];
    int jj = q*4;
    Bsh[jj][n]=v.x; Bsh[jj+1][n]=v.y; Bsh[jj+2][n]=v.z; Bsh[jj+3][n]=v.w;
  }
}

// ---------------- preprocessing ----------------------------------------------
__global__ void prep_zero_kernel(){
  int idx = blockIdx.x*blockDim.x + threadIdx.x;
  if (idx < LL*BB*HH){ g_hh[idx] = 0.f; g_c[idx] = 0.f; }
  if (idx == 0){ g_bar = 0u; g_flag1 = 0u; g_flag2 = 0u; }
}

__global__ void prep_in_kernel(const float* __restrict__ inp,
                               const float* __restrict__ boundary){
  int idx = blockIdx.x*blockDim.x + threadIdx.x;
  if (idx < TT*LL*BB){
    int b  = idx % BB;
    int kk = (idx / BB) % LL;
    int t  = idx / (BB*LL);
    const float* src = inp + (b*TT + t)*FF + kk*GG;
    bool any = false;
    #pragma unroll
    for (int j = 0; j < GG; j++){
      float v = src[j];
      bool nn = (v != v);
      any = any || (!nn);
      g_xg[idx*GG + j] = nn ? 0.f : v;
    }
    g_z[idx] = any ? 1 : 0;
  }
  if (idx < LL*TT) g_bt[idx] = (boundary[idx] > 0.5f) ? 1.f : 0.f;
}

__global__ void prep_allz_kernel(){
  int st = blockIdx.x*blockDim.x + threadIdx.x;
  if (st < TT*LL){
    unsigned char a = 1;
    for (int b = 0; b < BB; b++) a = (unsigned char)(a & g_z[st*BB + b]);
    g_allz[st] = a;
  }
}

// ---------------- grid barrier -----------------------------------------------
__device__ __forceinline__ void gbar(unsigned int tgt){
  __syncthreads();
  if (threadIdx.x == 0){
    __threadfence();
    atomicAdd(&g_bar, 1u);
    while (*((volatile unsigned int*)&g_bar) < tgt) __nanosleep(32);
  }
  __syncthreads();
  __threadfence();
}

// ---------------- persistent recurrence (unchanged, fp32) --------------------
__global__ void __launch_bounds__(256,1) recur_kernel(
    const float* __restrict__ W, const float* __restrict__ Z,
    const float* __restrict__ U, const float* __restrict__ V,
    const float* __restrict__ J, const float* __restrict__ bvec)
{
  __shared__ float Ash[32][68];
  __shared__ float Bsh[32][68];
  __shared__ float red[256];
  __shared__ float sflag[2];
  __shared__ unsigned char zsh[64];

  const int tid = threadIdx.x;
  const int cta = blockIdx.x;
  const int tx = tid & 15, ty = tid >> 4;
  unsigned int tgt = 0;

  for (int st = 0; st < TT*LL; st++){
    const int t = st >> 2, k = st & 3;

    float v = (t > 0 && tid < NREC) ? g_part[(st-LL)*NREC + tid] : 0.f;
    red[tid] = v; __syncthreads();
    #pragma unroll
    for (int s = 128; s > 0; s >>= 1){ if (tid < s) red[tid] += red[tid+s]; __syncthreads(); }
    if (tid == 0) sflag[0] = (t == 0) ? g_bt[k*TT] : ((red[0] > 16384.f) ? 1.f : 0.f);
    __syncthreads();
    v = (k > 0 && tid < NREC) ? g_part[(st-1)*NREC + tid] : 0.f;
    red[tid] = v; __syncthreads();
    #pragma unroll
    for (int s = 128; s > 0; s >>= 1){ if (tid < s) red[tid] += red[tid+s]; __syncthreads(); }
    if (tid == 0) sflag[1] = (k == 0) ? g_bt[t] : ((red[0] > 16384.f) ? 1.f : 0.f);
    if (tid < 64) zsh[tid] = g_z[st*BB + tid];
    __syncthreads();

    const bool p = sflag[0] >= 0.5f, l = sflag[1] >= 0.5f;
    const int mode = (!p && l) ? 1 : ((p && !l) ? 2 : ((p && l) ? 3 : 4));
    const float* bk = bvec + k*FIVEH;
    const int e = cta*256 + tid, eb = e >> 9, eh = e & 511;

    if (mode == 4){
      float o  = sigf(bk[3*HH + eh]);
      float cp = g_c[(k*BB + eb)*HH + eh];
      g_hh[((size_t)((t+1)*LL + k)*BB + eb)*HH + eh] = o * tanhf(cp);
      float sgv = clip01((bk[4*HH + eh] + 1.f)*0.5f);
      red[tid] = sgv; __syncthreads();
      #pragma unroll
      for (int s = 128; s > 0; s >>= 1){ if (tid < s) red[tid] += red[tid+s]; __syncthreads(); }
      if (tid == 0) g_part[st*NREC + cta] = red[0];
      tgt += NREC; gbar(tgt);
      continue;
    }

    const int ng = (mode == 1) ? 4 : 3;
    const int nT = ng*8;
    const bool az = (g_allz[st] != 0);

    if (cta < nT*4){
      const int split = cta / nT, ntile = cta - split*nT;
      const int n0 = ntile*64, loc = n0 >> 9, h0 = n0 & 511;
      const int g = (mode == 1) ? ((loc == 3) ? 4 : loc)
                                : ((loc == 0) ? 1 : ((loc == 1) ? 2 : 4));
      const size_t wr0 = (size_t)(g*HH + h0);
      const int jb = split*128;
      float acc[4][4] = {{0.f,0.f,0.f,0.f},{0.f,0.f,0.f,0.f},{0.f,0.f,0.f,0.f},{0.f,0.f,0.f,0.f}};

      const float* bA[3]; const float* bW[3]; int bws[3]; int bmm[3]; int nb = 0;
      {
        const int km = (mode == 1) ? k : ((k+1 < LL) ? k+1 : LL-1);
        bA[nb] = g_hh + ((size_t)(t*LL + km)*BB)*HH;
        bW[nb] = ((mode == 1) ? W : Z) + (size_t)k*FIVEH*HH + wr0*HH;
        bws[nb] = HH; bmm[nb] = 0; nb++;
      }
      if (mode != 2 && k > 0){
        const float* hlow = g_hh + ((size_t)((t+1)*LL + (k-1))*BB)*HH;
        bA[nb] = hlow; bW[nb] = U + (size_t)k*FIVEH*(HH+GG) + wr0*(HH+GG);
        bws[nb] = HH+GG; bmm[nb] = az ? 0 : 1; nb++;
        if (!az){
          bA[nb] = hlow; bW[nb] = V + (size_t)k*FIVEH*HH + wr0*HH;
          bws[nb] = HH; bmm[nb] = 2; nb++;
        }
      }
      for (int bi = 0; bi < nb; bi++){
        const float* A = bA[bi]; const float* Wr = bW[bi];
        const int ws = bws[bi], mm = bmm[bi];
        for (int j0 = 0; j0 < 128; j0 += 32){
          load_tiles_T<32>(A, HH, mm, zsh, jb + j0, Wr, ws, jb + j0, tid, Ash, Bsh);
          __syncthreads();
          mm_inner(Ash, Bsh, 32, ty, tx, acc);
          __syncthreads();
        }
      }
      if (split == 0){
        const float* A = g_xg + (size_t)st*BB*GG;
        const float* Wr; int ws, jbw;
        if (mode != 2){ Wr = U + (size_t)k*FIVEH*(HH+GG) + wr0*(HH+GG); ws = HH+GG; jbw = HH; }
        else          { Wr = J + (size_t)k*FIVEH*GG + wr0*GG;           ws = GG;    jbw = 0;  }
        load_tiles_T<16>(A, GG, 0, zsh, 0, Wr, ws, jbw, tid, Ash, Bsh);
        __syncthreads();
        mm_inner(Ash, Bsh, 16, ty, tx, acc);
        __syncthreads();
      }
      #pragma unroll
      for (int r = 0; r < 4; r++){
        float4 o = make_float4(acc[r][0], acc[r][1], acc[r][2], acc[r][3]);
        *(float4*)&g_pp[((size_t)split*BB + ty*4 + r)*(4*HH) + n0 + tx*4] = o;
      }
    }
    tgt += NREC; gbar(tgt);

    {
      const size_t pb = (size_t)eb*(4*HH) + eh;
      const size_t sp = (size_t)BB*4*HH;
      float a0 = ((g_pp[pb]        + g_pp[sp + pb])        + g_pp[2*sp + pb])        + g_pp[3*sp + pb];
      float a1 = ((g_pp[pb+HH]     + g_pp[sp + pb+HH])     + g_pp[2*sp + pb+HH])     + g_pp[3*sp + pb+HH];
      float a2 = ((g_pp[pb+2*HH]   + g_pp[sp + pb+2*HH])   + g_pp[2*sp + pb+2*HH])   + g_pp[3*sp + pb+2*HH];
      float a3 = 0.f;
      if (ng == 4)
        a3 = ((g_pp[pb+3*HH] + g_pp[sp + pb+3*HH]) + g_pp[2*sp + pb+3*HH]) + g_pp[3*sp + pb+3*HH];

      float cp = g_c[(k*BB + eb)*HH + eh];
      float cn, ps;
      if (mode == 1){
        float f  = sigf (a0 + bk[eh]);
        float gg = tanhf(a1 + bk[HH + eh]);
        float ii = sigf (a2 + bk[2*HH + eh]);
        ps = a3 + bk[4*HH + eh];
        cn = f*cp + ii*gg;
      } else {
        float gg = tanhf(a0 + bk[HH + eh]);
        float ii = sigf (a1 + bk[2*HH + eh]);
        ps = a2 + bk[4*HH + eh];
        cn = ii*gg;
      }
      g_c[(k*BB + eb)*HH + eh] = cn;
      g_hh[((size_t)((t+1)*LL + k)*BB + eb)*HH + eh] =
          g_hh[((size_t)(t*LL + k)*BB + eb)*HH + eh];
      float sgv = clip01((ps + 1.f)*0.5f);
      red[tid] = sgv; __syncthreads();
      #pragma unroll
      for (int s = 128; s > 0; s >>= 1){ if (tid < s) red[tid] += red[tid+s]; __syncthreads(); }
      if (tid == 0) g_part[st*NREC + cta] = red[0];
    }
    tgt += NREC; gbar(tgt);
  }
}

// ---------------- bf16 split conversions -------------------------------------
__global__ void conv_hcat_kernel(){
  int idx = blockIdx.x*blockDim.x + threadIdx.x;
  if (idx >= MTOT*512) return;
  int m = idx >> 9, f4 = (idx & 511);
  int f = f4*4;
  int b = m >> 7, t = m & 127;
  int kf = f >> 9, hf = f & 511;
  float4 v = *(const float4*)&g_hh[(((size_t)(t+1)*LL + kf)*BB + b)*HH + hf];
  union { __nv_bfloat16 e[4]; uint2 u; } wh, wl;
  bsplit(v.x, wh.e[0], wl.e[0]);
  bsplit(v.y, wh.e[1], wl.e[1]);
  bsplit(v.z, wh.e[2], wl.e[2]);
  bsplit(v.w, wh.e[3], wl.e[3]);
  *(uint2*)&g_Ahi[(size_t)m*2048 + f] = wh.u;
  *(uint2*)&g_Alo[(size_t)m*2048 + f] = wl.u;
}

__global__ void trans_split_kernel(const float* __restrict__ src,
                                   __nv_bfloat16* __restrict__ dhi,
                                   __nv_bfloat16* __restrict__ dlo,
                                   int R, int C){
  __shared__ float tl[32][33];
  const int z = blockIdx.z;
  const float* s = src + (size_t)z*R*C;
  __nv_bfloat16* oh = dhi + (size_t)z*R*C;
  __nv_bfloat16* ol = dlo + (size_t)z*R*C;
  int r0 = blockIdx.x*32, c0 = blockIdx.y*32;
  int tx = threadIdx.x, ty = threadIdx.y;
  #pragma unroll
  for (int i = 0; i < 4; i++)
    tl[ty + 8*i][tx] = s[(size_t)(r0 + ty + 8*i)*C + c0 + tx];
  __syncthreads();
  #pragma unroll
  for (int i = 0; i < 4; i++){
    float v = tl[tx][ty + 8*i];
    __nv_bfloat16 hi, lo; bsplit(v, hi, lo);
    size_t o = (size_t)(c0 + ty + 8*i)*R + r0 + tx;
    oh[o] = hi; ol[o] = lo;
  }
}

// ---------------- excitation: WMMA attempt -----------------------------------
__global__ void __launch_bounds__(256) e1_wmma_kernel(){
  __shared__ __align__(32) __nv_bfloat16 smbuf[4*128*SPAD];   // 40,960 B
  const int n0 = blockIdx.x*128, m0 = blockIdx.y*128;
  FragC acc[2][4];
  #pragma unroll
  for (int mi = 0; mi < 2; mi++)
    #pragma unroll
    for (int ni = 0; ni < 4; ni++) wmma::fill_fragment(acc[mi][ni], 0.f);

  wmma_core(smbuf,
            g_Ahi + (size_t)m0*2048, g_Alo + (size_t)m0*2048, 2048,
            g_QThi + (size_t)n0*2048, g_QTlo + (size_t)n0*2048, 2048,
            2048, acc);

  // epilogue: reuse dead tile smem as per-warp fp32 scratch (8*384*4 = 12,288 B)
  float* swp = (float*)smbuf;
  const int tid = threadIdx.x, lane = tid & 31, wid = tid >> 5;
  const int wm = wid & 3, wn = wid >> 2;
  const int kq = n0 >> 9, h0 = n0 & 511;
  float* wp = swp + wid*384;
  #pragma unroll
  for (int mi = 0; mi < 2; mi++){
    #pragma unroll
    for (int ni = 0; ni < 4; ni++){
      wmma::store_matrix_sync(wp, acc[mi][ni], 24, wmma::mem_row_major);
      __syncwarp();
      int r0 = m0 + wm*32 + mi*16;
      int c0 = h0 + wn*64 + ni*16;
      #pragma unroll
      for (int e = 0; e < 8; e++){
        int idx2 = e*32 + lane;
        int r = idx2 >> 4, c = idx2 & 15;
        float vv = sigf(wp[r*24 + c]);
        __nv_bfloat16 hi, lo; bsplit(vv, hi, lo);
        size_t o = ((size_t)kq*MTOT + r0 + r)*HH + c0 + c;
        g_R1hi[o] = hi; g_R1lo[o] = lo;
      }
      __syncwarp();
    }
  }
}

__global__ void __launch_bounds__(256) e2_wmma_kernel(){
  __shared__ __align__(32) __nv_bfloat16 smbuf[4*128*SPAD];
  const int n0 = blockIdx.x*128, m0 = blockIdx.y*128, kq = blockIdx.z;
  FragC acc[2][4];
  #pragma unroll
  for (int mi = 0; mi < 2; mi++)
    #pragma unroll
    for (int ni = 0; ni < 4; ni++) wmma::fill_fragment(acc[mi][ni], 0.f);

  wmma_core(smbuf,
            g_R1hi + ((size_t)kq*MTOT + m0)*HH, g_R1lo + ((size_t)kq*MTOT + m0)*HH, 512,
            g_RmThi + ((size_t)kq*HH + n0)*HH,  g_RmTlo + ((size_t)kq*HH + n0)*HH,  512,
            512, acc);

  const int wid = threadIdx.x >> 5;
  const int wm = wid & 3, wn = wid >> 2;
  #pragma unroll
  for (int mi = 0; mi < 2; mi++){
    #pragma unroll
    for (int ni = 0; ni < 4; ni++){
      int r0 = m0 + wm*32 + mi*16;
      int c0 = n0 + wn*64 + ni*16;
      wmma::store_matrix_sync(&g_mul1[((size_t)kq*MTOT + r0)*HH + c0],
                              acc[mi][ni], HH, wmma::mem_row_major);
    }
  }
}

// ---------------- verifiers (NaN-safe) + SIMT fallbacks ----------------------
__global__ void verify_e1_kernel(const float* __restrict__ Q){
  int s = blockIdx.x*blockDim.x + threadIdx.x;      // 4096 samples
  int m = (s*5) & 8191;
  int c = (s*131 + 7) & 2047;
  int kq = c >> 9, h = c & 511;
  int b = m >> 7, t = m & 127;
  float ref = 0.f;
  for (int f = 0; f < 2048; f++){
    int kf = f >> 9, hf = f & 511;
    float a = g_hh[(((size_t)(t+1)*LL + kf)*BB + b)*HH + hf];
    ref += a * Q[((size_t)kq*2048 + f)*512 + h];
  }
  float want = sigf(ref);
  size_t o = ((size_t)kq*MTOT + m)*HH + h;
  float got = __bfloat162float(g_R1hi[o]) + __bfloat162float(g_R1lo[o]);
  float d = fabsf(got - want);
  if (!(d <= 2e-3f)) atomicExch(&g_flag1, 1u);      // NaN also triggers
}

// fallback e1: the R5-proven SIMT kernel, writing split bf16
__global__ void __launch_bounds__(256) e1_fb_kernel(const float* __restrict__ Q){
  if (g_flag1 == 0u) return;
  __shared__ float Ash[32][68];
  __shared__ float Bsh[32][68];
  const int tid = threadIdx.x, tx = tid & 15, ty = tid >> 4;
  const int n0 = blockIdx.x*64, m0 = blockIdx.y*64;
  const int kq = n0 >> 9, nh0 = n0 & 511;
  const int bB = m0 >> 7, t0 = m0 & 127;
  float acc[4][4] = {{0.f,0.f,0.f,0.f},{0.f,0.f,0.f,0.f},{0.f,0.f,0.f,0.f},{0.f,0.f,0.f,0.f}};
  for (int f0 = 0; f0 < LL*HH; f0 += 32){
    const int kf = f0 >> 9, hf = f0 & 511;
    const float* abase = g_hh + ((size_t)(t0+1)*LL + kf)*BB*HH + (size_t)bB*HH + hf;
    #pragma unroll
    for (int id = tid; id < 512; id += 256){
      int mi = id >> 3, q = id & 7;
      float4 v = *(const float4*)(abase + (size_t)mi*(LL*BB*HH) + q*4);
      int jj = q*4;
      Ash[jj][mi]=v.x; Ash[jj+1][mi]=v.y; Ash[jj+2][mi]=v.z; Ash[jj+3][mi]=v.w;
    }
    #pragma unroll
    for (int id = tid; id < 512; id += 256){
      int j = id >> 4, qn = id & 15;
      float4 v = *(const float4*)&Q[((size_t)kq*(LL*HH) + f0 + j)*HH + nh0 + qn*4];
      *(float4*)&Bsh[j][qn*4] = v;
    }
    __syncthreads();
    mm_inner(Ash, Bsh, 32, ty, tx, acc);
    __syncthreads();
  }
  #pragma unroll
  for (int r = 0; r < 4; r++){
    #pragma unroll
    for (int c = 0; c < 4; c++){
      float vv = sigf(acc[r][c]);
      __nv_bfloat16 hi, lo; bsplit(vv, hi, lo);
      size_t o = ((size_t)kq*MTOT + m0 + ty*4 + r)*HH + nh0 + tx*4 + c;
      g_R1hi[o] = hi; g_R1lo[o] = lo;
    }
  }
}

__global__ void verify_e2_kernel(const float* __restrict__ Rm){
  int s = blockIdx.x*blockDim.x + threadIdx.x;      // 4096 samples
  int m = (s*5) & 8191;
  int g = (s*131 + 7) & 511;
  int kq = s & 3;
  float ref = 0.f;
  for (int h = 0; h < 512; h++){
    size_t o = ((size_t)kq*MTOT + m)*HH + h;
    float r1 = __bfloat162float(g_R1hi[o]) + __bfloat162float(g_R1lo[o]);
    ref += r1 * Rm[((size_t)kq*512 + h)*512 + g];
  }
  float got = g_mul1[((size_t)kq*MTOT + m)*HH + g];
  float d = fabsf(got - ref);
  if (!(d <= 5e-3f)) atomicExch(&g_flag2, 1u);
}

// fallback e2: SIMT, A = R1(hi+lo), B = Rm[kq]; 64x64 tiles
__global__ void __launch_bounds__(256) e2_fb_kernel(const float* __restrict__ Rm){
  if (g_flag2 == 0u) return;
  __shared__ float Ash[32][68];
  __shared__ float Bsh[32][68];
  const int tid = threadIdx.x, tx = tid & 15, ty = tid >> 4;
  const int n0 = blockIdx.x*64, m0 = blockIdx.y*64, kq = blockIdx.z;
  float acc[4][4] = {{0.f,0.f,0.f,0.f},{0.f,0.f,0.f,0.f},{0.f,0.f,0.f,0.f},{0.f,0.f,0.f,0.f}};
  for (int f0 = 0; f0 < HH; f0 += 32){
    #pragma unroll
    for (int id = tid; id < 2048; id += 256){
      int mi = id >> 5, j = id & 31;
      size_t o = ((size_t)kq*MTOT + m0 + mi)*HH + f0 + j;
      Ash[j][mi] = __bfloat162float(g_R1hi[o]) + __bfloat162float(g_R1lo[o]);
    }
    #pragma unroll
    for (int id = tid; id < 512; id += 256){
      int j = id >> 4, qn = id & 15;
      float4 v = *(const float4*)&Rm[((size_t)kq*HH + f0 + j)*HH + n0 + qn*4];
      *(float4*)&Bsh[j][qn*4] = v;
    }
    __syncthreads();
    mm_inner(Ash, Bsh, 32, ty, tx, acc);
    __syncthreads();
  }
  #pragma unroll
  for (int r = 0; r < 4; r++){
    float4 o = make_float4(acc[r][0], acc[r][1], acc[r][2], acc[r][3]);
    *(float4*)&g_mul1[((size_t)kq*MTOT + m0 + ty*4 + r)*HH + n0 + tx*4] = o;
  }
}

// excited[m][n] = relu( sum_k mul1[k][m][n] * h_k[m][n] )
__global__ void fuse_excited_kernel(){
  int idx = blockIdx.x*blockDim.x + threadIdx.x;
  if (idx >= MTOT*128) return;
  int m = idx >> 7, n = (idx & 127) << 2;
  int b = m >> 7, t = m & 127;
  float4 tot = make_float4(0.f, 0.f, 0.f, 0.f);
  #pragma unroll
  for (int k = 0; k < LL; k++){
    float4 mu = *(const float4*)&g_mul1[((size_t)k*MTOT + m)*HH + n];
    float4 hv = *(const float4*)&g_hh[(((size_t)(t+1)*LL + k)*BB + b)*HH + n];
    tot.x += mu.x*hv.x; tot.y += mu.y*hv.y; tot.z += mu.z*hv.z; tot.w += mu.w*hv.w;
  }
  float4 o = make_float4(fmaxf(tot.x,0.f), fmaxf(tot.y,0.f), fmaxf(tot.z,0.f), fmaxf(tot.w,0.f));
  *(float4*)&g_excited[(size_t)m*HH + n] = o;
}

// e3: out[m][n] = excited[m][:] @ Wo[n][:] + bo[n]
__global__ void __launch_bounds__(256) e3_kernel(const float* __restrict__ Wo,
                                                 const float* __restrict__ bo,
                                                 float* __restrict__ out){
  __shared__ float Ash[32][68];
  __shared__ float Bsh[32][68];
  const int tid = threadIdx.x, tx = tid & 15, ty = tid >> 4;
  const int m0 = blockIdx.x*64;
  float acc[4][4] = {{0.f,0.f,0.f,0.f},{0.f,0.f,0.f,0.f},{0.f,0.f,0.f,0.f},{0.f,0.f,0.f,0.f}};
  for (int f0 = 0; f0 < HH; f0 += 32){
    load_tiles_T<32>(g_excited + (size_t)m0*HH, HH, 0, (const unsigned char*)g_z, f0,
                     Wo, HH, f0, tid, Ash, Bsh);
    __syncthreads();
    mm_inner(Ash, Bsh, 32, ty, tx, acc);
    __syncthreads();
  }
  #pragma unroll
  for (int r = 0; r < 4; r++){
    int n = tx*4;
    float4 o = make_float4(acc[r][0] + bo[n], acc[r][1] + bo[n+1],
                           acc[r][2] + bo[n+2], acc[r][3] + bo[n+3]);
    *(float4*)&out[(size_t)(m0 + ty*4 + r)*FF + n] = o;
  }
}

// ---------------- launch -----------------------------------------------------
extern "C" void kernel_launch(void* const* d_in, const int* in_sizes, int n_in,
                              void* d_out, int out_size) {
  const float* inp      = (const float*)d_in[0];
  const float* W        = (const float*)d_in[1];
  const float* Z        = (const float*)d_in[2];
  const float* U        = (const float*)d_in[3];
  const float* V        = (const float*)d_in[4];
  const float* J        = (const float*)d_in[5];
  const float* bvec     = (const float*)d_in[6];
  const float* boundary = (const float*)d_in[7];
  const float* Q        = (const float*)d_in[8];
  const float* Rm       = (const float*)d_in[9];
  const float* Wo       = (const float*)d_in[10];
  const float* bo       = (const float*)d_in[11];
  float* out            = (float*)d_out;

  prep_zero_kernel<<<512, 256>>>();
  prep_in_kernel<<<128, 256>>>(inp, boundary);
  prep_allz_kernel<<<2, 256>>>();

  trans_split_kernel<<<dim3(64, 16, 4), dim3(32, 8)>>>(Q,  g_QThi,  g_QTlo,  2048, 512);
  trans_split_kernel<<<dim3(16, 16, 4), dim3(32, 8)>>>(Rm, g_RmThi, g_RmTlo, 512,  512);

  recur_kernel<<<NREC, 256>>>(W, Z, U, V, J, bvec);

  conv_hcat_kernel<<<(MTOT*512)/256, 256>>>();
  e1_wmma_kernel<<<dim3(16, 64), 256>>>();
  verify_e1_kernel<<<16, 256>>>(Q);
  e1_fb_kernel<<<dim3(32, 128), 256>>>(Q);
  e2_wmma_kernel<<<dim3(4, 64, 4), 256>>>();
  verify_e2_kernel<<<16, 256>>>(Rm);
  e2_fb_kernel<<<dim3(8, 128, 4), 256>>>(Rm);
  fuse_excited_kernel<<<(MTOT*128)/256, 256>>>();
  e3_kernel<<<128, 256>>>(Wo, bo, out);
}